// round 11
// baseline (speedup 1.0000x reference)
#include <cuda_runtime.h>
#include <cuda_fp16.h>
#include <cstdint>

// out[b*64+n][o] = (1/16) * sum_f x[b*64+n][f] * W[n][f][o]
// 64 GEMMs: A_n [4096 x 256] (row stride 16384 floats) @ B_n [256 x 256].
// Single-pass fp16 HMMA (fp32 accum). 256 threads, 8 warps @ 64x64 warp tile,
// BM=128 x BN=256, BK=64 chunks, 3-stage cp.async pipeline,
// warp-staggered k-half order to break inter-warp phase locking.

#define NUM_NODES 64
#define BATCH     4096
#define RS        16384

#define BM 128
#define NCHUNK 4
#define THREADS 256

// stage layout (bytes): A 16K ([128 rows x 64 k] fp16, 128B rows, SW128)
//                       B 32K ([256 rows x 64 k] fp16, 128B rows, SW128)
#define STG  49152
#define OA   0
#define OB   16384
#define NSTAGE 3
#define SMEM_TOTAL (NSTAGE * STG)   // 147456

// W pre-converted fp16, pre-swizzled 128B-row tiles:
// g_Wh[(node*4 + chunk)*32768 + swz(n*128 + kl*2)],  kl = f - chunk*64
__device__ __align__(16) unsigned char g_Wh[NUM_NODES * 4 * 32768];

// ======================= helpers =======================
__device__ __forceinline__ uint32_t swz(uint32_t x) { return x ^ ((x >> 3) & 0x70); }
__device__ __forceinline__ uint32_t smem_u32(const void* p) {
    uint32_t a;
    asm("{ .reg .u64 t; cvta.to.shared.u64 t, %1; cvt.u32.u64 %0, t; }" : "=r"(a) : "l"(p));
    return a;
}
__device__ __forceinline__ void cp16(uint32_t d, const void* s) {
    asm volatile("cp.async.cg.shared.global [%0], [%1], 16;" :: "r"(d), "l"(s) : "memory");
}
__device__ __forceinline__ void ldmx4(uint32_t* r, uint32_t a) {
    asm volatile("ldmatrix.sync.aligned.m8n8.x4.shared.b16 {%0,%1,%2,%3}, [%4];"
                 : "=r"(r[0]), "=r"(r[1]), "=r"(r[2]), "=r"(r[3]) : "r"(a));
}
__device__ __forceinline__ void mma16816(float* c, const uint32_t* a, uint32_t b0, uint32_t b1) {
    asm volatile(
        "mma.sync.aligned.m16n8k16.row.col.f32.f16.f16.f32 "
        "{%0,%1,%2,%3}, {%4,%5,%6,%7}, {%8,%9}, {%0,%1,%2,%3};"
        : "+f"(c[0]), "+f"(c[1]), "+f"(c[2]), "+f"(c[3])
        : "r"(a[0]), "r"(a[1]), "r"(a[2]), "r"(a[3]), "r"(b0), "r"(b1));
}
__device__ __forceinline__ uint32_t packh2(float a, float b) {
    __half2 h = __floats2half2_rn(a, b);
    return *reinterpret_cast<uint32_t*>(&h);
}
__device__ __forceinline__ void sts16(uint32_t addr, uint32_t a, uint32_t b, uint32_t c, uint32_t d) {
    asm volatile("st.shared.v4.b32 [%0], {%1,%2,%3,%4};"
                 :: "r"(addr), "r"(a), "r"(b), "r"(c), "r"(d) : "memory");
}

// ======================= prep: W -> fp16, swizzled 128B-row tiles =======================
__global__ __launch_bounds__(256)
void prep_w(const float* __restrict__ W) {
    __shared__ __align__(16) unsigned char sh[32768];
    const int node = blockIdx.x >> 2;
    const int c    = blockIdx.x & 3;
    const int o    = threadIdx.x;            // n index, coalesced across lanes

    const float* src = W + (size_t)node * 65536 + (size_t)c * 64 * 256 + o;
    #pragma unroll 4
    for (int fl = 0; fl < 64; fl++) {
        float v = src[(size_t)fl * 256];
        const uint32_t ad = swz((uint32_t)(o * 128 + fl * 2));
        *reinterpret_cast<__half*>(sh + ad) = __float2half_rn(v);
    }
    __syncthreads();

    const size_t off = (size_t)blockIdx.x * 32768;
    const float4* ph = reinterpret_cast<const float4*>(sh);
    float4* dh = reinterpret_cast<float4*>(g_Wh + off);
    #pragma unroll
    for (int i = 0; i < 8; i++) {
        const int idx = threadIdx.x + i * 256;
        dh[idx] = ph[idx];
    }
}

// ======================= main GEMM =======================
__global__ __launch_bounds__(THREADS, 1)
void node_gemm_hmma(const float* __restrict__ x, float* __restrict__ out) {
    extern __shared__ unsigned char sm[];
    const uint32_t smb = smem_u32(sm);
    const int t    = threadIdx.x;
    const int lane = t & 31;
    const int wid  = t >> 5;
    const int wm   = wid >> 2;      // 0..1 -> m offset wm*64
    const int wn   = wid & 3;       // 0..3 -> n offset wn*64
    const int node = blockIdx.y;
    const int m0   = blockIdx.x * BM;

    // de-phase: the two warps on each SMSP (wid, wid+4) start 2 k-halves apart
    const int hoff = (wid + ((wid >> 2) << 1)) & 3;

    // ---- A global-load role: thread t owns row t>>1, k-half (t&1)*32 ----
    const int arow = t >> 1;
    const int ahalf = (t & 1) * 32;
    const float* ag = x + (size_t)node * 256 + (size_t)(m0 + arow) * RS + ahalf;
    uint32_t asts[4];
    #pragma unroll
    for (int i = 0; i < 4; i++)
        asts[i] = swz((uint32_t)(arow * 128 + ahalf * 2 + i * 16));

    // ---- fragment ldmatrix LINEAR base offsets (128B rows); swz per k-half use ----
    const int aq = lane >> 3;
    const uint32_t aoff_lin = (uint32_t)((wm * 64 + (aq & 1) * 8 + (lane & 7)) * 128 +
                                         (aq >> 1) * 16);
    const uint32_t boff_lin = (uint32_t)((wn * 64 + ((lane >> 4) & 1) * 8 + (lane & 7)) * 128 +
                                         ((lane >> 3) & 1) * 16);

    float acc[4][8][4];
    #pragma unroll
    for (int mi = 0; mi < 4; mi++)
        #pragma unroll
        for (int nf = 0; nf < 8; nf++)
            #pragma unroll
            for (int r = 0; r < 4; r++) acc[mi][nf][r] = 0.f;

    auto cpB = [&](int c, int s) {
        const unsigned char* gh = g_Wh + (size_t)(node * 4 + c) * 32768;
        const uint32_t sb = smb + s * STG + OB;
        #pragma unroll
        for (int j = 0; j < 8; j++) {
            const uint32_t o = (uint32_t)(t + j * 256) * 16;
            cp16(sb + o, gh + o);
        }
        asm volatile("cp.async.commit_group;" ::: "memory");
    };
    auto ldA = [&](int c, float4* v) {
        #pragma unroll
        for (int j = 0; j < 8; j++)
            v[j] = *reinterpret_cast<const float4*>(ag + c * 64 + j * 4);
    };
    auto stsA = [&](int s, const float4* v) {
        const uint32_t sb = smb + s * STG + OA;
        #pragma unroll
        for (int i = 0; i < 4; i++)
            sts16(sb + asts[i],
                  packh2(v[2*i].x, v[2*i].y),     packh2(v[2*i].z, v[2*i].w),
                  packh2(v[2*i+1].x, v[2*i+1].y), packh2(v[2*i+1].z, v[2*i+1].w));
    };

    // ---- prologue ----
    cpB(0, 0);
    cpB(1, 1);
    {
        float4 a0[8];
        ldA(0, a0);
        stsA(0, a0);
    }
    asm volatile("cp.async.wait_group 1;" ::: "memory");
    __syncthreads();

    // ---- mainloop: 4 chunks; k-halves visited in warp-staggered order ----
    for (int c = 0; c < NCHUNK; c++) {
        const int s = c % 3;
        const uint32_t sb = smb + s * STG;

        float4 av[8];
        if (c + 1 < NCHUNK) ldA(c + 1, av);            // DRAM LDG hidden under MMAs
        if (c + 2 < NCHUNK) cpB(c + 2, (c + 2) % 3);   // L2 -> smem, 2 chunks ahead

        #pragma unroll
        for (int hs = 0; hs < 4; hs++) {
            const int h = (hs + hoff) & 3;             // staggered k-half
            const uint32_t aswz = swz(aoff_lin + h * 32);
            const uint32_t bswz = swz(boff_lin + h * 32);
            uint32_t A[4][4], B[4][4];
            #pragma unroll
            for (int mi = 0; mi < 4; mi++) ldmx4(A[mi], sb + OA + aswz + mi * 2048);
            #pragma unroll
            for (int g = 0; g < 4; g++) ldmx4(B[g], sb + OB + bswz + g * 2048);

            #pragma unroll
            for (int g = 0; g < 4; g++)
                #pragma unroll
                for (int gg = 0; gg < 2; gg++) {
                    const int nf = 2 * g + gg;
                    #pragma unroll
                    for (int mi = 0; mi < 4; mi++)
                        mma16816(acc[mi][nf], A[mi], B[g][gg * 2], B[g][gg * 2 + 1]);
                }
        }

        if (c + 1 < NCHUNK) {
            stsA((c + 1) % 3, av);
            if (c + 2 < NCHUNK) {
                asm volatile("cp.async.wait_group 1;" ::: "memory");
            } else {
                asm volatile("cp.async.wait_group 0;" ::: "memory");
            }
            __syncthreads();
        }
    }

    // ---- epilogue: registers -> gmem, scale 1/16 ----
    const float sc = 0.0625f;
    float* ob = out + (size_t)node * 256;
    const int ecol0 = wn * 64 + (lane & 3) * 2;
    #pragma unroll
    for (int mi = 0; mi < 4; mi++) {
        const int erow = m0 + wm * 64 + mi * 16 + (lane >> 2);
        #pragma unroll
        for (int nf = 0; nf < 8; nf++) {
            float* p0 = ob + (size_t)erow * RS + ecol0 + nf * 8;
            float* p1 = p0 + (size_t)8 * RS;
            float2 v0, v1;
            v0.x = acc[mi][nf][0] * sc; v0.y = acc[mi][nf][1] * sc;
            v1.x = acc[mi][nf][2] * sc; v1.y = acc[mi][nf][3] * sc;
            *reinterpret_cast<float2*>(p0) = v0;
            *reinterpret_cast<float2*>(p1) = v1;
        }
    }
}

// ======================= launch =======================
extern "C" void kernel_launch(void* const* d_in, const int* in_sizes, int n_in,
                              void* d_out, int out_size)
{
    const float* x = (const float*)d_in[0];   // [262144, 256] f32
    const float* W = (const float*)d_in[2];   // [64, 256, 256] f32
    float*     out = (float*)d_out;

    cudaFuncSetAttribute(node_gemm_hmma, cudaFuncAttributeMaxDynamicSharedMemorySize, SMEM_TOTAL);

    prep_w<<<NUM_NODES * 4, 256>>>(W);
    node_gemm_hmma<<<dim3(BATCH / BM, NUM_NODES), THREADS, SMEM_TOTAL>>>(x, out);
}

// round 15
// speedup vs baseline: 1.1227x; 1.1227x over previous
#include <cuda_runtime.h>
#include <cuda_fp16.h>
#include <cstdint>

// out[b*64+n][o] = (1/16) * sum_f x[b*64+n][f] * W[n][f][o]
// 64 GEMMs: A_n [4096 x 256] (row stride 16384 floats) @ B_n [256 x 256].
// Single-pass fp16 HMMA (fp32 accum). 512 threads, 16 warps @ 32x64 warp tile,
// BM=128 x BN=256 CTA tile, BK=32 chunks, 4-stage cp.async pipeline.

#define NUM_NODES 64
#define BATCH     4096
#define RS        16384

#define BM 128
#define NCHUNK 8
#define THREADS 512

// stage layout (bytes): A 8K ([128 rows x 32 k] fp16, 64B rows, SW128)
//                       B 16K ([256 rows x 32 k] fp16, 64B rows, SW128)
#define STG  24576
#define OA   0
#define OB   8192
#define NSTAGE 4
#define SMEM_TOTAL (NSTAGE * STG)   // 98304

// W pre-converted fp16, pre-swizzled: g_Wh[(node*8+chunk)*16384 + swz(n*64 + kl*2)]
__device__ __align__(16) unsigned char g_Wh[NUM_NODES * 8 * 16384];

// ======================= helpers =======================
__device__ __forceinline__ uint32_t swz(uint32_t x) { return x ^ ((x >> 3) & 0x70); }
__device__ __forceinline__ uint32_t smem_u32(const void* p) {
    uint32_t a;
    asm("{ .reg .u64 t; cvta.to.shared.u64 t, %1; cvt.u32.u64 %0, t; }" : "=r"(a) : "l"(p));
    return a;
}
__device__ __forceinline__ void cp16(uint32_t d, const void* s) {
    asm volatile("cp.async.cg.shared.global [%0], [%1], 16;" :: "r"(d), "l"(s) : "memory");
}
__device__ __forceinline__ void ldmx4(uint32_t* r, uint32_t a) {
    asm volatile("ldmatrix.sync.aligned.m8n8.x4.shared.b16 {%0,%1,%2,%3}, [%4];"
                 : "=r"(r[0]), "=r"(r[1]), "=r"(r[2]), "=r"(r[3]) : "r"(a));
}
__device__ __forceinline__ void mma16816(float* c, const uint32_t* a, uint32_t b0, uint32_t b1) {
    asm volatile(
        "mma.sync.aligned.m16n8k16.row.col.f32.f16.f16.f32 "
        "{%0,%1,%2,%3}, {%4,%5,%6,%7}, {%8,%9}, {%0,%1,%2,%3};"
        : "+f"(c[0]), "+f"(c[1]), "+f"(c[2]), "+f"(c[3])
        : "r"(a[0]), "r"(a[1]), "r"(a[2]), "r"(a[3]), "r"(b0), "r"(b1));
}
__device__ __forceinline__ uint32_t packh2(float a, float b) {
    __half2 h = __floats2half2_rn(a, b);
    return *reinterpret_cast<uint32_t*>(&h);
}
__device__ __forceinline__ void sts16(uint32_t addr, uint32_t a, uint32_t b, uint32_t c, uint32_t d) {
    asm volatile("st.shared.v4.b32 [%0], {%1,%2,%3,%4};"
                 :: "r"(addr), "r"(a), "r"(b), "r"(c), "r"(d) : "memory");
}

// ======================= prep: W -> fp16, swizzled tiles =======================
__global__ __launch_bounds__(256)
void prep_w(const float* __restrict__ W) {
    __shared__ __align__(16) unsigned char sh[16384];
    const int node = blockIdx.x >> 3;
    const int c    = blockIdx.x & 7;
    const int o    = threadIdx.x;            // n index, coalesced across lanes

    const float* src = W + (size_t)node * 65536 + (size_t)c * 32 * 256 + o;
    #pragma unroll 4
    for (int fl = 0; fl < 32; fl++) {
        float v = src[(size_t)fl * 256];
        const uint32_t ad = swz((uint32_t)(o * 64 + fl * 2));
        *reinterpret_cast<__half*>(sh + ad) = __float2half_rn(v);
    }
    __syncthreads();

    const size_t off = (size_t)blockIdx.x * 16384;
    const float4* ph = reinterpret_cast<const float4*>(sh);
    float4* dh = reinterpret_cast<float4*>(g_Wh + off);
    #pragma unroll
    for (int i = 0; i < 4; i++) {
        const int idx = threadIdx.x + i * 256;
        dh[idx] = ph[idx];
    }
}

// ======================= main GEMM =======================
__global__ __launch_bounds__(THREADS, 1)
void node_gemm_hmma(const float* __restrict__ x, float* __restrict__ out) {
    extern __shared__ unsigned char sm[];
    const uint32_t smb = smem_u32(sm);
    const int t    = threadIdx.x;
    const int lane = t & 31;
    const int wid  = t >> 5;        // 0..15
    const int wm   = wid >> 2;      // 0..3 -> m offset wm*32
    const int wn   = wid & 3;       // 0..3 -> n offset wn*64
    const int node = blockIdx.y;
    const int m0   = blockIdx.x * BM;

    // ---- A global-load role: thread t owns row t>>2, 8 floats at (t&3)*8 ----
    const int arow = t >> 2;
    const int aq4  = t & 3;
    const float* ag = x + (size_t)node * 256 + (size_t)(m0 + arow) * RS + aq4 * 8;
    const uint32_t asts = swz((uint32_t)(arow * 64 + aq4 * 16));

    // ---- fragment ldmatrix LINEAR base offsets (64B rows); swz per k-half use ----
    const int aq = lane >> 3;
    const uint32_t aoff_lin = (uint32_t)((wm * 32 + (aq & 1) * 8 + (lane & 7)) * 64 +
                                         (aq >> 1) * 16);
    const uint32_t boff_lin = (uint32_t)((wn * 64 + ((lane >> 4) & 1) * 8 + (lane & 7)) * 64 +
                                         ((lane >> 3) & 1) * 16);

    float acc[2][8][4];
    #pragma unroll
    for (int mi = 0; mi < 2; mi++)
        #pragma unroll
        for (int nf = 0; nf < 8; nf++)
            #pragma unroll
            for (int r = 0; r < 4; r++) acc[mi][nf][r] = 0.f;

    auto cpB = [&](int c, int s) {
        const unsigned char* gh = g_Wh + (size_t)(node * 8 + c) * 16384;
        const uint32_t sb = smb + s * STG + OB;
        #pragma unroll
        for (int j = 0; j < 2; j++) {
            const uint32_t o = (uint32_t)(t + j * 512) * 16;
            cp16(sb + o, gh + o);
        }
        asm volatile("cp.async.commit_group;" ::: "memory");
    };
    auto ldA = [&](int c, float4* v) {
        v[0] = *reinterpret_cast<const float4*>(ag + c * 32);
        v[1] = *reinterpret_cast<const float4*>(ag + c * 32 + 4);
    };
    auto stsA = [&](int s, const float4* v) {
        const uint32_t sb = smb + s * STG + OA;
        sts16(sb + asts, packh2(v[0].x, v[0].y), packh2(v[0].z, v[0].w),
                         packh2(v[1].x, v[1].y), packh2(v[1].z, v[1].w));
    };

    // ---- prologue: B chunks 0..2 in flight, A chunks 0,1 staged ----
    cpB(0, 0);
    cpB(1, 1);
    cpB(2, 2);
    {
        float4 a0[2];
        ldA(0, a0);
        stsA(0, a0);
        float4 a1[2];
        ldA(1, a1);
        stsA(1, a1);
    }
    asm volatile("cp.async.wait_group 2;" ::: "memory");
    __syncthreads();

    // ---- mainloop: one barrier per chunk ----
    for (int c = 0; c < NCHUNK; c++) {
        const int s = c & 3;
        const uint32_t sb = smb + s * STG;

        float4 av[2];
        if (c + 2 < NCHUNK) ldA(c + 2, av);          // DRAM LDG hidden under MMAs
        if (c + 3 < NCHUNK) cpB(c + 3, (c + 3) & 3);

        #pragma unroll
        for (int h = 0; h < 2; h++) {
            const uint32_t aswz = swz(aoff_lin + h * 32);
            const uint32_t bswz = swz(boff_lin + h * 32);
            uint32_t A[2][4], B[4][4];
            ldmx4(A[0], sb + OA + aswz);
            ldmx4(A[1], sb + OA + aswz + 1024);
            #pragma unroll
            for (int g = 0; g < 4; g++) ldmx4(B[g], sb + OB + bswz + g * 1024);

            #pragma unroll
            for (int g = 0; g < 4; g++)
                #pragma unroll
                for (int gg = 0; gg < 2; gg++) {
                    const int nf = 2 * g + gg;
                    mma16816(acc[0][nf], A[0], B[g][gg * 2], B[g][gg * 2 + 1]);
                    mma16816(acc[1][nf], A[1], B[g][gg * 2], B[g][gg * 2 + 1]);
                }
        }

        if (c + 2 < NCHUNK) stsA((c + 2) & 3, av);
        if (c < NCHUNK - 1) {
            if (c + 3 < NCHUNK) {
                asm volatile("cp.async.wait_group 2;" ::: "memory");
            } else if (c + 2 < NCHUNK) {
                asm volatile("cp.async.wait_group 1;" ::: "memory");
            } else {
                asm volatile("cp.async.wait_group 0;" ::: "memory");
            }
            __syncthreads();
        }
    }

    // ---- epilogue: registers -> gmem, scale 1/16 ----
    const float sc = 0.0625f;
    float* ob = out + (size_t)node * 256;
    const int ecol0 = wn * 64 + (lane & 3) * 2;
    #pragma unroll
    for (int mi = 0; mi < 2; mi++) {
        const int erow = m0 + wm * 32 + mi * 16 + (lane >> 2);
        #pragma unroll
        for (int nf = 0; nf < 8; nf++) {
            float* p0 = ob + (size_t)erow * RS + ecol0 + nf * 8;
            float* p1 = p0 + (size_t)8 * RS;
            float2 v0, v1;
            v0.x = acc[mi][nf][0] * sc; v0.y = acc[mi][nf][1] * sc;
            v1.x = acc[mi][nf][2] * sc; v1.y = acc[mi][nf][3] * sc;
            *reinterpret_cast<float2*>(p0) = v0;
            *reinterpret_cast<float2*>(p1) = v1;
        }
    }
}

// ======================= launch =======================
extern "C" void kernel_launch(void* const* d_in, const int* in_sizes, int n_in,
                              void* d_out, int out_size)
{
    const float* x = (const float*)d_in[0];   // [262144, 256] f32
    const float* W = (const float*)d_in[2];   // [64, 256, 256] f32
    float*     out = (float*)d_out;

    cudaFuncSetAttribute(node_gemm_hmma, cudaFuncAttributeMaxDynamicSharedMemorySize, SMEM_TOTAL);

    prep_w<<<NUM_NODES * 8, 256>>>(W);
    node_gemm_hmma<<<dim3(BATCH / BM, NUM_NODES), THREADS, SMEM_TOTAL>>>(x, out);
}

// round 16
// speedup vs baseline: 1.1785x; 1.0498x over previous
#include <cuda_runtime.h>
#include <cuda_fp16.h>
#include <cstdint>

// out[b*64+n][o] = (1/16) * sum_f x[b*64+n][f] * W[n][f][o]
// 64 GEMMs: A_n [4096 x 256] (row stride 16384 floats) @ B_n [256 x 256].
// Single-pass fp16 HMMA (fp32 accum). 256 threads, 8 warps @ 32x64 warp tile,
// BM=64 x BN=256 CTA tile, BK=32, 4-stage cp.async pipeline, 2 CTAs/SM.

#define NUM_NODES 64
#define BATCH     4096
#define RS        16384

#define BM 64
#define NCHUNK 8
#define THREADS 256

// stage layout (bytes): A 4K ([64 rows x 32 k] fp16, 64B rows, SW128)
//                       B 16K ([256 rows x 32 k] fp16, 64B rows, SW128)
#define STG  20480
#define OA   0
#define OB   4096
#define NSTAGE 4
#define SMEM_TOTAL (NSTAGE * STG)   // 81920 -> 2 CTAs/SM

// W pre-converted fp16, pre-swizzled: g_Wh[(node*8+chunk)*16384 + swz(n*64 + kl*2)]
__device__ __align__(16) unsigned char g_Wh[NUM_NODES * 8 * 16384];

// ======================= helpers =======================
__device__ __forceinline__ uint32_t swz(uint32_t x) { return x ^ ((x >> 3) & 0x70); }
__device__ __forceinline__ uint32_t smem_u32(const void* p) {
    uint32_t a;
    asm("{ .reg .u64 t; cvta.to.shared.u64 t, %1; cvt.u32.u64 %0, t; }" : "=r"(a) : "l"(p));
    return a;
}
__device__ __forceinline__ void cp16(uint32_t d, const void* s) {
    asm volatile("cp.async.cg.shared.global [%0], [%1], 16;" :: "r"(d), "l"(s) : "memory");
}
__device__ __forceinline__ void ldmx4(uint32_t* r, uint32_t a) {
    asm volatile("ldmatrix.sync.aligned.m8n8.x4.shared.b16 {%0,%1,%2,%3}, [%4];"
                 : "=r"(r[0]), "=r"(r[1]), "=r"(r[2]), "=r"(r[3]) : "r"(a));
}
__device__ __forceinline__ void mma16816(float* c, const uint32_t* a, uint32_t b0, uint32_t b1) {
    asm volatile(
        "mma.sync.aligned.m16n8k16.row.col.f32.f16.f16.f32 "
        "{%0,%1,%2,%3}, {%4,%5,%6,%7}, {%8,%9}, {%0,%1,%2,%3};"
        : "+f"(c[0]), "+f"(c[1]), "+f"(c[2]), "+f"(c[3])
        : "r"(a[0]), "r"(a[1]), "r"(a[2]), "r"(a[3]), "r"(b0), "r"(b1));
}
__device__ __forceinline__ uint32_t packh2(float a, float b) {
    __half2 h = __floats2half2_rn(a, b);
    return *reinterpret_cast<uint32_t*>(&h);
}
__device__ __forceinline__ void sts16(uint32_t addr, uint32_t a, uint32_t b, uint32_t c, uint32_t d) {
    asm volatile("st.shared.v4.b32 [%0], {%1,%2,%3,%4};"
                 :: "r"(addr), "r"(a), "r"(b), "r"(c), "r"(d) : "memory");
}

// ======================= prep: W -> fp16, swizzled tiles =======================
__global__ __launch_bounds__(256)
void prep_w(const float* __restrict__ W) {
    __shared__ __align__(16) unsigned char sh[16384];
    const int node = blockIdx.x >> 3;
    const int c    = blockIdx.x & 7;
    const int o    = threadIdx.x;            // n index, coalesced across lanes

    const float* src = W + (size_t)node * 65536 + (size_t)c * 32 * 256 + o;
    #pragma unroll 4
    for (int fl = 0; fl < 32; fl++) {
        float v = src[(size_t)fl * 256];
        const uint32_t ad = swz((uint32_t)(o * 64 + fl * 2));
        *reinterpret_cast<__half*>(sh + ad) = __float2half_rn(v);
    }
    __syncthreads();

    const size_t off = (size_t)blockIdx.x * 16384;
    const float4* ph = reinterpret_cast<const float4*>(sh);
    float4* dh = reinterpret_cast<float4*>(g_Wh + off);
    #pragma unroll
    for (int i = 0; i < 4; i++) {
        const int idx = threadIdx.x + i * 256;
        dh[idx] = ph[idx];
    }
}

// ======================= main GEMM =======================
__global__ __launch_bounds__(THREADS, 2)
void node_gemm_hmma(const float* __restrict__ x, float* __restrict__ out) {
    extern __shared__ unsigned char sm[];
    const uint32_t smb = smem_u32(sm);
    const int t    = threadIdx.x;
    const int lane = t & 31;
    const int wid  = t >> 5;        // 0..7
    const int wm   = wid >> 2;      // 0..1 -> m offset wm*32
    const int wn   = wid & 3;       // 0..3 -> n offset wn*64
    const int node = blockIdx.y;
    const int m0   = blockIdx.x * BM;

    // ---- A global-load role: thread t owns row t>>2 (0..63), 8 floats at (t&3)*8 ----
    const int arow = t >> 2;
    const int aq4  = t & 3;
    const float* ag = x + (size_t)node * 256 + (size_t)(m0 + arow) * RS + aq4 * 8;
    const uint32_t asts = swz((uint32_t)(arow * 64 + aq4 * 16));

    // ---- fragment ldmatrix LINEAR base offsets (64B rows); swz per k-half use ----
    const int aq = lane >> 3;
    const uint32_t aoff_lin = (uint32_t)((wm * 32 + (aq & 1) * 8 + (lane & 7)) * 64 +
                                         (aq >> 1) * 16);
    const uint32_t boff_lin = (uint32_t)((wn * 64 + ((lane >> 4) & 1) * 8 + (lane & 7)) * 64 +
                                         ((lane >> 3) & 1) * 16);

    float acc[2][8][4];
    #pragma unroll
    for (int mi = 0; mi < 2; mi++)
        #pragma unroll
        for (int nf = 0; nf < 8; nf++)
            #pragma unroll
            for (int r = 0; r < 4; r++) acc[mi][nf][r] = 0.f;

    auto cpB = [&](int c, int s) {
        const unsigned char* gh = g_Wh + (size_t)(node * 8 + c) * 16384;
        const uint32_t sb = smb + s * STG + OB;
        #pragma unroll
        for (int j = 0; j < 4; j++) {
            const uint32_t o = (uint32_t)(t + j * 256) * 16;
            cp16(sb + o, gh + o);
        }
        asm volatile("cp.async.commit_group;" ::: "memory");
    };
    auto ldA = [&](int c, float4* v) {
        v[0] = *reinterpret_cast<const float4*>(ag + c * 32);
        v[1] = *reinterpret_cast<const float4*>(ag + c * 32 + 4);
    };
    auto stsA = [&](int s, const float4* v) {
        const uint32_t sb = smb + s * STG + OA;
        sts16(sb + asts, packh2(v[0].x, v[0].y), packh2(v[0].z, v[0].w),
                         packh2(v[1].x, v[1].y), packh2(v[1].z, v[1].w));
    };

    // ---- prologue: B chunks 0..2 in flight, A chunks 0,1 staged ----
    cpB(0, 0);
    cpB(1, 1);
    cpB(2, 2);
    {
        float4 a0[2];
        ldA(0, a0);
        stsA(0, a0);
        float4 a1[2];
        ldA(1, a1);
        stsA(1, a1);
    }
    asm volatile("cp.async.wait_group 2;" ::: "memory");
    __syncthreads();

    // ---- mainloop: one barrier per chunk ----
    for (int c = 0; c < NCHUNK; c++) {
        const int s = c & 3;
        const uint32_t sb = smb + s * STG;

        float4 av[2];
        if (c + 2 < NCHUNK) ldA(c + 2, av);          // DRAM LDG hidden under MMAs
        if (c + 3 < NCHUNK) cpB(c + 3, (c + 3) & 3);

        #pragma unroll
        for (int h = 0; h < 2; h++) {
            const uint32_t aswz = swz(aoff_lin + h * 32);
            const uint32_t bswz = swz(boff_lin + h * 32);
            uint32_t A[2][4], B[4][4];
            ldmx4(A[0], sb + OA + aswz);
            ldmx4(A[1], sb + OA + aswz + 1024);
            #pragma unroll
            for (int g = 0; g < 4; g++) ldmx4(B[g], sb + OB + bswz + g * 1024);

            #pragma unroll
            for (int g = 0; g < 4; g++)
                #pragma unroll
                for (int gg = 0; gg < 2; gg++) {
                    const int nf = 2 * g + gg;
                    mma16816(acc[0][nf], A[0], B[g][gg * 2], B[g][gg * 2 + 1]);
                    mma16816(acc[1][nf], A[1], B[g][gg * 2], B[g][gg * 2 + 1]);
                }
        }

        if (c + 2 < NCHUNK) stsA((c + 2) & 3, av);
        if (c < NCHUNK - 1) {
            if (c + 3 < NCHUNK) {
                asm volatile("cp.async.wait_group 2;" ::: "memory");
            } else if (c + 2 < NCHUNK) {
                asm volatile("cp.async.wait_group 1;" ::: "memory");
            } else {
                asm volatile("cp.async.wait_group 0;" ::: "memory");
            }
            __syncthreads();
        }
    }

    // ---- epilogue: registers -> gmem, scale 1/16 ----
    const float sc = 0.0625f;
    float* ob = out + (size_t)node * 256;
    const int ecol0 = wn * 64 + (lane & 3) * 2;
    #pragma unroll
    for (int mi = 0; mi < 2; mi++) {
        const int erow = m0 + wm * 32 + mi * 16 + (lane >> 2);
        #pragma unroll
        for (int nf = 0; nf < 8; nf++) {
            float* p0 = ob + (size_t)erow * RS + ecol0 + nf * 8;
            float* p1 = p0 + (size_t)8 * RS;
            float2 v0, v1;
            v0.x = acc[mi][nf][0] * sc; v0.y = acc[mi][nf][1] * sc;
            v1.x = acc[mi][nf][2] * sc; v1.y = acc[mi][nf][3] * sc;
            *reinterpret_cast<float2*>(p0) = v0;
            *reinterpret_cast<float2*>(p1) = v1;
        }
    }
}

// ======================= launch =======================
extern "C" void kernel_launch(void* const* d_in, const int* in_sizes, int n_in,
                              void* d_out, int out_size)
{
    const float* x = (const float*)d_in[0];   // [262144, 256] f32
    const float* W = (const float*)d_in[2];   // [64, 256, 256] f32
    float*     out = (float*)d_out;

    cudaFuncSetAttribute(node_gemm_hmma, cudaFuncAttributeMaxDynamicSharedMemorySize, SMEM_TOTAL);

    prep_w<<<NUM_NODES * 8, 256>>>(W);
    node_gemm_hmma<<<dim3(BATCH / BM, NUM_NODES), THREADS, SMEM_TOTAL>>>(x, out);
}